// round 6
// baseline (speedup 1.0000x reference)
#include <cuda_runtime.h>
#include <cuda_bf16.h>
#include <mma.h>

using namespace nvcuda;

#define S   2048
#define DM  2048
#define H   32
#define G   8
#define DK  64
#define HD  (H*DK)   // 2048
#define GD  (G*DK)   // 512
#define NT  (S/128)  // 16 col-tiles per row

// Scratch (no cudaMalloc allowed)
__device__ float g_qh[(size_t)S*HD];
__device__ float g_kh[(size_t)S*GD];
__device__ float g_vh[(size_t)S*GD];
__device__ float g_outh[(size_t)S*HD];
__device__ float g_pm[(size_t)H*NT*S];   // per-tile max
__device__ float g_ps[(size_t)H*NT*S];   // per-tile sumexp
__device__ float g_m[(size_t)H*S];       // row max
__device__ float g_inv[(size_t)H*S];     // 1/row sum

using FragA  = wmma::fragment<wmma::matrix_a, 16,16,16, __nv_bfloat16, wmma::row_major>;
using FragBr = wmma::fragment<wmma::matrix_b, 16,16,16, __nv_bfloat16, wmma::row_major>;
using FragBc = wmma::fragment<wmma::matrix_b, 16,16,16, __nv_bfloat16, wmma::col_major>;
using FragC  = wmma::fragment<wmma::accumulator, 16,16,16, float>;

__device__ __forceinline__ void split2(float x, __nv_bfloat16& h, __nv_bfloat16& l) {
    h = __float2bfloat16_rn(x);
    l = __float2bfloat16_rn(x - __bfloat162float(h));
}
__device__ __forceinline__ void store_split4(float4 v, __nv_bfloat16* h, __nv_bfloat16* l) {
    split2(v.x, h[0], l[0]); split2(v.y, h[1], l[1]);
    split2(v.z, h[2], l[2]); split2(v.w, h[3], l[3]);
}

// ---------------------------------------------------------------------------
// GEMM + bias: C[M,N] = A[M,K] @ W[K,N] + bias.  bf16-split tensor cores.
// 128x128 tile, BK=32, 256 threads (8 warps), warp tile 32x64.
// ---------------------------------------------------------------------------
__global__ __launch_bounds__(256)
void gemm_bias_k(const float* __restrict__ A,
                 const float* __restrict__ W,
                 const float* __restrict__ bias,
                 float* __restrict__ C,
                 int M, int N, int K)
{
    __shared__ __align__(16) __nv_bfloat16 As_hi[128][40];
    __shared__ __align__(16) __nv_bfloat16 As_lo[128][40];
    __shared__ __align__(16) __nv_bfloat16 Bs_hi[32][136];
    __shared__ __align__(16) __nv_bfloat16 Bs_lo[32][136];
    __shared__ __align__(16) float biasTile[16][136];

    const int tid  = threadIdx.x;
    const int warp = tid >> 5;
    const int m0 = blockIdx.y * 128;
    const int n0 = blockIdx.x * 128;
    const int wm = warp >> 1;
    const int wn = warp & 1;
    const int m_base = wm * 32;
    const int n_base = wn * 64;

    const int la_m  = tid >> 1;
    const int la_k4 = (tid & 1) * 16;
    const int lb_k  = tid >> 3;
    const int lb_n  = (tid & 7) * 16;

    const float* Ap = A + (size_t)(m0 + la_m) * K + la_k4;
    const float* Bp = W + (size_t)lb_k * N + n0 + lb_n;

    for (int idx = tid; idx < 16 * 128; idx += 256) {
        int r = idx >> 7, c = idx & 127;
        biasTile[r][c] = bias[n0 + c];
    }
    __syncthreads();

    FragC acc[2][4];
    #pragma unroll
    for (int i = 0; i < 2; i++)
        #pragma unroll
        for (int j = 0; j < 4; j++)
            wmma::load_matrix_sync(acc[i][j], &biasTile[0][n_base + j*16], 136, wmma::mem_row_major);

    float4 pa[4], pb[4];
    #pragma unroll
    for (int q = 0; q < 4; q++) {
        pa[q] = *(const float4*)(Ap + 4*q);
        pb[q] = *(const float4*)(Bp + 4*q);
    }

    for (int k0 = 0; k0 < K; k0 += 32) {
        #pragma unroll
        for (int q = 0; q < 4; q++) {
            store_split4(pa[q], &As_hi[la_m][la_k4 + 4*q], &As_lo[la_m][la_k4 + 4*q]);
            store_split4(pb[q], &Bs_hi[lb_k][lb_n + 4*q], &Bs_lo[lb_k][lb_n + 4*q]);
        }
        __syncthreads();

        if (k0 + 32 < K) {
            #pragma unroll
            for (int q = 0; q < 4; q++) {
                pa[q] = *(const float4*)(Ap + k0 + 32 + 4*q);
                pb[q] = *(const float4*)(Bp + (size_t)(k0 + 32) * N + 4*q);
            }
        }

        #pragma unroll
        for (int kf = 0; kf < 2; kf++) {
            FragA a_hi[2], a_lo[2];
            #pragma unroll
            for (int i = 0; i < 2; i++) {
                wmma::load_matrix_sync(a_hi[i], &As_hi[m_base + i*16][kf*16], 40);
                wmma::load_matrix_sync(a_lo[i], &As_lo[m_base + i*16][kf*16], 40);
            }
            #pragma unroll
            for (int j = 0; j < 4; j++) {
                FragBr b_hi, b_lo;
                wmma::load_matrix_sync(b_hi, &Bs_hi[kf*16][n_base + j*16], 136);
                wmma::load_matrix_sync(b_lo, &Bs_lo[kf*16][n_base + j*16], 136);
                #pragma unroll
                for (int i = 0; i < 2; i++) {
                    wmma::mma_sync(acc[i][j], a_hi[i], b_hi, acc[i][j]);
                    wmma::mma_sync(acc[i][j], a_hi[i], b_lo, acc[i][j]);
                    wmma::mma_sync(acc[i][j], a_lo[i], b_hi, acc[i][j]);
                }
            }
        }
        __syncthreads();
    }

    #pragma unroll
    for (int i = 0; i < 2; i++)
        #pragma unroll
        for (int j = 0; j < 4; j++)
            wmma::store_matrix_sync(C + (size_t)(m0 + m_base + i*16) * N + n0 + n_base + j*16,
                                    acc[i][j], N, wmma::mem_row_major);
}

// ---------------------------------------------------------------------------
// Scores + per-tile softmax stats. 128x128 tile, 512 threads, 4x4 warps.
// Writes raw masked/scaled scores to attn; per-(row,tile) max & sumexp to
// g_pm/g_ps.
// ---------------------------------------------------------------------------
__global__ __launch_bounds__(512)
void scores_stats_k(const float* __restrict__ qh,
                    const float* __restrict__ kh,
                    const unsigned int* __restrict__ mask,
                    float* __restrict__ attn,
                    float* __restrict__ pm,
                    float* __restrict__ ps)
{
    extern __shared__ char dyns[];
    __nv_bfloat16* Qh_s = (__nv_bfloat16*)dyns;        // [128][72]
    __nv_bfloat16* Ql_s = Qh_s + 128*72;
    __nv_bfloat16* Kh_s = Ql_s + 128*72;
    __nv_bfloat16* Kl_s = Kh_s + 128*72;
    float* stage = (float*)dyns;                       // [128][132] reuse

    const int tid  = threadIdx.x;
    const int warp = tid >> 5;
    const int j0 = blockIdx.x * 128;
    const int i0 = blockIdx.y * 128;
    const int h  = blockIdx.z;
    const int g  = h >> 2;
    const int wm = warp >> 2;
    const int wn = warp & 3;
    const int m_base = wm * 32;
    const int n_base = wn * 32;

    const int l_s = tid >> 2;          // 0..127
    const int l_d = (tid & 3) * 16;    // 0,16,32,48

    const float* Qp = qh + (size_t)(i0 + l_s) * HD + h * DK + l_d;
    const float* Kp = kh + (size_t)(j0 + l_s) * GD + g * DK + l_d;

    #pragma unroll
    for (int q = 0; q < 4; q++) {
        float4 vq = *(const float4*)(Qp + 4*q);
        vq.x *= 0.125f; vq.y *= 0.125f; vq.z *= 0.125f; vq.w *= 0.125f;
        store_split4(vq, &Qh_s[l_s*72 + l_d + 4*q], &Ql_s[l_s*72 + l_d + 4*q]);
        float4 vk = *(const float4*)(Kp + 4*q);
        store_split4(vk, &Kh_s[l_s*72 + l_d + 4*q], &Kl_s[l_s*72 + l_d + 4*q]);
    }
    __syncthreads();

    FragC acc[2][2];
    #pragma unroll
    for (int i = 0; i < 2; i++)
        #pragma unroll
        for (int j = 0; j < 2; j++)
            wmma::fill_fragment(acc[i][j], 0.0f);

    #pragma unroll
    for (int kf = 0; kf < 4; kf++) {
        FragA a_hi[2], a_lo[2];
        #pragma unroll
        for (int i = 0; i < 2; i++) {
            wmma::load_matrix_sync(a_hi[i], &Qh_s[(m_base + i*16)*72 + kf*16], 72);
            wmma::load_matrix_sync(a_lo[i], &Ql_s[(m_base + i*16)*72 + kf*16], 72);
        }
        #pragma unroll
        for (int j = 0; j < 2; j++) {
            FragBc b_hi, b_lo;
            wmma::load_matrix_sync(b_hi, &Kh_s[(n_base + j*16)*72 + kf*16], 72);
            wmma::load_matrix_sync(b_lo, &Kl_s[(n_base + j*16)*72 + kf*16], 72);
            #pragma unroll
            for (int i = 0; i < 2; i++) {
                wmma::mma_sync(acc[i][j], a_hi[i], b_hi, acc[i][j]);
                wmma::mma_sync(acc[i][j], a_hi[i], b_lo, acc[i][j]);
                wmma::mma_sync(acc[i][j], a_lo[i], b_hi, acc[i][j]);
            }
        }
    }

    __syncthreads();
    #pragma unroll
    for (int i = 0; i < 2; i++)
        #pragma unroll
        for (int j = 0; j < 2; j++)
            wmma::store_matrix_sync(&stage[(m_base + i*16)*132 + n_base + j*16],
                                    acc[i][j], 132, wmma::mem_row_major);
    __syncthreads();

    // stats + masked write: 4 threads per row, 32 cols each
    const int r  = tid >> 2;
    const int qd = tid & 3;
    const size_t gr = (size_t)(i0 + r);
    float* ap = attn + (size_t)h * S * S;

    float mx = -3.4e38f;
    #pragma unroll
    for (int b = 0; b < 8; b++) {
        const int c = qd * 32 + b * 4;
        float4 sv = *(const float4*)&stage[r*132 + c];
        uint4 mv = *(const uint4*)(mask + gr * S + j0 + c);
        sv.x = mv.x ? sv.x : -1e9f;
        sv.y = mv.y ? sv.y : -1e9f;
        sv.z = mv.z ? sv.z : -1e9f;
        sv.w = mv.w ? sv.w : -1e9f;
        mx = fmaxf(mx, fmaxf(fmaxf(sv.x, sv.y), fmaxf(sv.z, sv.w)));
        *(float4*)&stage[r*132 + c] = sv;
        *(float4*)&ap[gr * S + j0 + c] = sv;
    }
    mx = fmaxf(mx, __shfl_xor_sync(0xffffffffu, mx, 1));
    mx = fmaxf(mx, __shfl_xor_sync(0xffffffffu, mx, 2));

    float sm = 0.0f;
    #pragma unroll
    for (int b = 0; b < 8; b++) {
        const int c = qd * 32 + b * 4;
        float4 sv = *(const float4*)&stage[r*132 + c];
        sm += __expf(sv.x - mx) + __expf(sv.y - mx)
            + __expf(sv.z - mx) + __expf(sv.w - mx);
    }
    sm += __shfl_xor_sync(0xffffffffu, sm, 1);
    sm += __shfl_xor_sync(0xffffffffu, sm, 2);

    if (qd == 0) {
        const size_t sidx = ((size_t)h * NT + blockIdx.x) * S + gr;
        pm[sidx] = mx;
        ps[sidx] = sm;
    }
}

// ---------------------------------------------------------------------------
// Combine per-tile stats -> row max + 1/rowsum.
// ---------------------------------------------------------------------------
__global__ __launch_bounds__(256)
void reduce_k(const float* __restrict__ pm,
              const float* __restrict__ ps,
              float* __restrict__ mrow,
              float* __restrict__ invrow)
{
    const int idx = blockIdx.x * 256 + threadIdx.x;   // 0..H*S-1
    const int h = idx >> 11;
    const int s = idx & (S - 1);
    const float* pmp = pm + (size_t)h * NT * S + s;
    const float* psp = ps + (size_t)h * NT * S + s;

    float m = -3.4e38f;
    #pragma unroll
    for (int t = 0; t < NT; t++) m = fmaxf(m, pmp[(size_t)t * S]);
    float sum = 0.0f;
    #pragma unroll
    for (int t = 0; t < NT; t++) sum += psp[(size_t)t * S] * __expf(pmp[(size_t)t * S] - m);

    mrow[idx]   = m;
    invrow[idx] = 1.0f / sum;
}

// ---------------------------------------------------------------------------
// Fused normalize + PV. 128 rows x 64 cols per block, K=S in 128-chunks.
// Reads raw scores, writes normalized attn, accumulates P@V in tensor cores.
// ---------------------------------------------------------------------------
__global__ __launch_bounds__(256)
void pv_norm_k(float* __restrict__ attn,
               const float* __restrict__ vh,
               const float* __restrict__ mrow,
               const float* __restrict__ invrow,
               float* __restrict__ outh)
{
    extern __shared__ char dyns[];
    __nv_bfloat16* Ph = (__nv_bfloat16*)dyns;     // [128][136]
    __nv_bfloat16* Pl = Ph + 128*136;
    __nv_bfloat16* Vh = Pl + 128*136;             // [128][72]
    __nv_bfloat16* Vl = Vh + 128*72;

    const int tid  = threadIdx.x;
    const int warp = tid >> 5;
    const int i0 = blockIdx.x * 128;
    const int h  = blockIdx.y;
    const int g  = h >> 2;
    const int wm = warp >> 1;
    const int wn = warp & 1;
    const int m_base = wm * 32;
    const int n_base = wn * 32;

    const int l_s = tid >> 1;            // 0..127 (row for P)
    const int l_d = (tid & 1) * 64;      // 0 or 64 (col half)
    const int lv_k = tid >> 1;           // 0..127 (k-row for V)
    const int lv_d = (tid & 1) * 32;     // 0 or 32

    const float mr = mrow[(size_t)h * S + i0 + l_s];
    const float ir = invrow[(size_t)h * S + i0 + l_s];

    float* ap = attn + (size_t)h * S * S + (size_t)(i0 + l_s) * S + l_d;
    const float* vp = vh + (size_t)lv_k * GD + g * DK + lv_d;

    FragC acc[2][2];
    #pragma unroll
    for (int i = 0; i < 2; i++)
        #pragma unroll
        for (int j = 0; j < 2; j++)
            wmma::fill_fragment(acc[i][j], 0.0f);

    for (int k0 = 0; k0 < S; k0 += 128) {
        // P: normalize, write back, split to smem
        #pragma unroll
        for (int q = 0; q < 16; q++) {
            float4 x = *(const float4*)(ap + k0 + 4*q);
            float4 p;
            p.x = __expf(x.x - mr) * ir;
            p.y = __expf(x.y - mr) * ir;
            p.z = __expf(x.z - mr) * ir;
            p.w = __expf(x.w - mr) * ir;
            *(float4*)(ap + k0 + 4*q) = p;
            store_split4(p, &Ph[l_s*136 + l_d + 4*q], &Pl[l_s*136 + l_d + 4*q]);
        }
        // V tile
        #pragma unroll
        for (int q = 0; q < 8; q++) {
            float4 v = *(const float4*)(vp + (size_t)k0 * GD + 4*q);
            store_split4(v, &Vh[lv_k*72 + lv_d + 4*q], &Vl[lv_k*72 + lv_d + 4*q]);
        }
        __syncthreads();

        #pragma unroll
        for (int kf = 0; kf < 8; kf++) {
            FragA a_hi[2], a_lo[2];
            #pragma unroll
            for (int i = 0; i < 2; i++) {
                wmma::load_matrix_sync(a_hi[i], &Ph[(m_base + i*16)*136 + kf*16], 136);
                wmma::load_matrix_sync(a_lo[i], &Pl[(m_base + i*16)*136 + kf*16], 136);
            }
            #pragma unroll
            for (int j = 0; j < 2; j++) {
                FragBr b_hi, b_lo;
                wmma::load_matrix_sync(b_hi, &Vh[(kf*16)*72 + n_base + j*16], 72);
                wmma::load_matrix_sync(b_lo, &Vl[(kf*16)*72 + n_base + j*16], 72);
                #pragma unroll
                for (int i = 0; i < 2; i++) {
                    wmma::mma_sync(acc[i][j], a_hi[i], b_hi, acc[i][j]);
                    wmma::mma_sync(acc[i][j], a_hi[i], b_lo, acc[i][j]);
                    wmma::mma_sync(acc[i][j], a_lo[i], b_hi, acc[i][j]);
                }
            }
        }
        __syncthreads();
    }

    #pragma unroll
    for (int i = 0; i < 2; i++)
        #pragma unroll
        for (int j = 0; j < 2; j++)
            wmma::store_matrix_sync(outh + (size_t)(i0 + m_base + i*16) * HD + h * DK + n_base + j*16,
                                    acc[i][j], HD, wmma::mem_row_major);
}

// ---------------------------------------------------------------------------
extern "C" void kernel_launch(void* const* d_in, const int* in_sizes, int n_in,
                              void* d_out, int out_size)
{
    const float*        q    = (const float*)d_in[0];
    const float*        k    = (const float*)d_in[1];
    const float*        v    = (const float*)d_in[2];
    const unsigned int* mask = (const unsigned int*)d_in[3];
    const float*        wq   = (const float*)d_in[4];
    const float*        bq   = (const float*)d_in[5];
    const float*        wk   = (const float*)d_in[6];
    const float*        bk   = (const float*)d_in[7];
    const float*        wv   = (const float*)d_in[8];
    const float*        bv   = (const float*)d_in[9];
    const float*        wo   = (const float*)d_in[10];
    const float*        bo   = (const float*)d_in[11];

    float* out  = (float*)d_out;
    float* attn = out + (size_t)S * DM;   // outputs: [out | attn]

    float *qh, *kh, *vh, *outh, *pm, *ps, *mrow, *invrow;
    cudaGetSymbolAddress((void**)&qh,     g_qh);
    cudaGetSymbolAddress((void**)&kh,     g_kh);
    cudaGetSymbolAddress((void**)&vh,     g_vh);
    cudaGetSymbolAddress((void**)&outh,   g_outh);
    cudaGetSymbolAddress((void**)&pm,     g_pm);
    cudaGetSymbolAddress((void**)&ps,     g_ps);
    cudaGetSymbolAddress((void**)&mrow,   g_m);
    cudaGetSymbolAddress((void**)&invrow, g_inv);

    const int scores_smem = 4 * 128 * 72 * (int)sizeof(__nv_bfloat16);       // 73728
    const int pv_smem     = (2 * 128 * 136 + 2 * 128 * 72) * (int)sizeof(__nv_bfloat16); // 106496
    cudaFuncSetAttribute(scores_stats_k, cudaFuncAttributeMaxDynamicSharedMemorySize, scores_smem);
    cudaFuncSetAttribute(pv_norm_k, cudaFuncAttributeMaxDynamicSharedMemorySize, pv_smem);

    // Projections
    gemm_bias_k<<<dim3(HD / 128, S / 128), 256>>>(q, wq, bq, qh, S, HD, DM);
    gemm_bias_k<<<dim3(GD / 128, S / 128), 256>>>(k, wk, bk, kh, S, GD, DM);
    gemm_bias_k<<<dim3(GD / 128, S / 128), 256>>>(v, wv, bv, vh, S, GD, DM);

    // Raw masked scores + tile stats
    scores_stats_k<<<dim3(S / 128, S / 128, H), 512, scores_smem>>>(qh, kh, mask, attn, pm, ps);

    // Row stats
    reduce_k<<<(H * S) / 256, 256>>>(pm, ps, mrow, invrow);

    // Normalize attn in place + P@V
    pv_norm_k<<<dim3(S / 128, H), 256, pv_smem>>>(attn, vh, mrow, invrow, outh);

    // Output projection
    gemm_bias_k<<<dim3(DM / 128, S / 128), 256>>>(outh, wo, bo, out, S, DM, HD);
}

// round 7
// speedup vs baseline: 1.7522x; 1.7522x over previous
#include <cuda_runtime.h>
#include <cuda_bf16.h>
#include <mma.h>

using namespace nvcuda;

#define S   2048
#define DM  2048
#define H   32
#define G   8
#define DK  64
#define HD  (H*DK)   // 2048
#define GD  (G*DK)   // 512

// Scratch (no cudaMalloc allowed)
__device__ float g_qh[(size_t)S*HD];
__device__ float g_kh[(size_t)S*GD];
__device__ float g_vh[(size_t)S*GD];
__device__ float g_outh[(size_t)S*HD];

using FragA  = wmma::fragment<wmma::matrix_a, 16,16,16, __nv_bfloat16, wmma::row_major>;
using FragBr = wmma::fragment<wmma::matrix_b, 16,16,16, __nv_bfloat16, wmma::row_major>;
using FragBc = wmma::fragment<wmma::matrix_b, 16,16,16, __nv_bfloat16, wmma::col_major>;
using FragC  = wmma::fragment<wmma::accumulator, 16,16,16, float>;

__device__ __forceinline__ void split2(float x, __nv_bfloat16& h, __nv_bfloat16& l) {
    h = __float2bfloat16_rn(x);
    l = __float2bfloat16_rn(x - __bfloat162float(h));
}
__device__ __forceinline__ void store_split4(float4 v, __nv_bfloat16* h, __nv_bfloat16* l) {
    split2(v.x, h[0], l[0]); split2(v.y, h[1], l[1]);
    split2(v.z, h[2], l[2]); split2(v.w, h[3], l[3]);
}

// ---------------------------------------------------------------------------
// GEMM + bias: C[M,N] = A[M,K] @ W[K,N] + bias.  bf16-split tensor cores.
// 128x128 tile, BK=32, 256 threads (8 warps), warp tile 32x64.
// ---------------------------------------------------------------------------
__global__ __launch_bounds__(256)
void gemm_bias_k(const float* __restrict__ A,
                 const float* __restrict__ W,
                 const float* __restrict__ bias,
                 float* __restrict__ C,
                 int M, int N, int K)
{
    __shared__ __align__(16) __nv_bfloat16 As_hi[128][40];
    __shared__ __align__(16) __nv_bfloat16 As_lo[128][40];
    __shared__ __align__(16) __nv_bfloat16 Bs_hi[32][136];
    __shared__ __align__(16) __nv_bfloat16 Bs_lo[32][136];
    __shared__ __align__(16) float biasTile[16][136];

    const int tid  = threadIdx.x;
    const int warp = tid >> 5;
    const int m0 = blockIdx.y * 128;
    const int n0 = blockIdx.x * 128;
    const int wm = warp >> 1;
    const int wn = warp & 1;
    const int m_base = wm * 32;
    const int n_base = wn * 64;

    const int la_m  = tid >> 1;
    const int la_k4 = (tid & 1) * 16;
    const int lb_k  = tid >> 3;
    const int lb_n  = (tid & 7) * 16;

    const float* Ap = A + (size_t)(m0 + la_m) * K + la_k4;
    const float* Bp = W + (size_t)lb_k * N + n0 + lb_n;

    for (int idx = tid; idx < 16 * 128; idx += 256) {
        int r = idx >> 7, c = idx & 127;
        biasTile[r][c] = bias[n0 + c];
    }
    __syncthreads();

    FragC acc[2][4];
    #pragma unroll
    for (int i = 0; i < 2; i++)
        #pragma unroll
        for (int j = 0; j < 4; j++)
            wmma::load_matrix_sync(acc[i][j], &biasTile[0][n_base + j*16], 136, wmma::mem_row_major);

    float4 pa[4], pb[4];
    #pragma unroll
    for (int q = 0; q < 4; q++) {
        pa[q] = *(const float4*)(Ap + 4*q);
        pb[q] = *(const float4*)(Bp + 4*q);
    }

    for (int k0 = 0; k0 < K; k0 += 32) {
        #pragma unroll
        for (int q = 0; q < 4; q++) {
            store_split4(pa[q], &As_hi[la_m][la_k4 + 4*q], &As_lo[la_m][la_k4 + 4*q]);
            store_split4(pb[q], &Bs_hi[lb_k][lb_n + 4*q], &Bs_lo[lb_k][lb_n + 4*q]);
        }
        __syncthreads();

        if (k0 + 32 < K) {
            #pragma unroll
            for (int q = 0; q < 4; q++) {
                pa[q] = *(const float4*)(Ap + k0 + 32 + 4*q);
                pb[q] = *(const float4*)(Bp + (size_t)(k0 + 32) * N + 4*q);
            }
        }

        #pragma unroll
        for (int kf = 0; kf < 2; kf++) {
            FragA a_hi[2], a_lo[2];
            #pragma unroll
            for (int i = 0; i < 2; i++) {
                wmma::load_matrix_sync(a_hi[i], &As_hi[m_base + i*16][kf*16], 40);
                wmma::load_matrix_sync(a_lo[i], &As_lo[m_base + i*16][kf*16], 40);
            }
            #pragma unroll
            for (int j = 0; j < 4; j++) {
                FragBr b_hi, b_lo;
                wmma::load_matrix_sync(b_hi, &Bs_hi[kf*16][n_base + j*16], 136);
                wmma::load_matrix_sync(b_lo, &Bs_lo[kf*16][n_base + j*16], 136);
                #pragma unroll
                for (int i = 0; i < 2; i++) {
                    wmma::mma_sync(acc[i][j], a_hi[i], b_hi, acc[i][j]);
                    wmma::mma_sync(acc[i][j], a_hi[i], b_lo, acc[i][j]);
                    wmma::mma_sync(acc[i][j], a_lo[i], b_hi, acc[i][j]);
                }
            }
        }
        __syncthreads();
    }

    #pragma unroll
    for (int i = 0; i < 2; i++)
        #pragma unroll
        for (int j = 0; j < 4; j++)
            wmma::store_matrix_sync(C + (size_t)(m0 + m_base + i*16) * N + n0 + n_base + j*16,
                                    acc[i][j], N, wmma::mem_row_major);
}

// ---------------------------------------------------------------------------
// Scores: raw scaled scores attn[h,i,j] = (Qh[i,:].Kg[j,:]) / 8 (scale folded
// into Q). Accumulators stored DIRECTLY to global — no smem stage, no mask
// (mask handled in softmax). 128x128 per block, 8 warps, warp tile 32x64.
// ---------------------------------------------------------------------------
__global__ __launch_bounds__(256)
void scores_k(const float* __restrict__ qh,
              const float* __restrict__ kh,
              float* __restrict__ attn)
{
    extern __shared__ char dyns[];
    __nv_bfloat16* Qh_s = (__nv_bfloat16*)dyns;        // [128][72]
    __nv_bfloat16* Ql_s = Qh_s + 128*72;
    __nv_bfloat16* Kh_s = Ql_s + 128*72;
    __nv_bfloat16* Kl_s = Kh_s + 128*72;

    const int tid  = threadIdx.x;
    const int warp = tid >> 5;
    const int j0 = blockIdx.x * 128;
    const int i0 = blockIdx.y * 128;
    const int h  = blockIdx.z;
    const int g  = h >> 2;
    const int wm = warp >> 1;
    const int wn = warp & 1;
    const int m_base = wm * 32;
    const int n_base = wn * 64;

    const int l_s = tid >> 1;          // 0..127
    const int l_d = (tid & 1) * 32;    // 0 or 32

    const float* Qp = qh + (size_t)(i0 + l_s) * HD + h * DK + l_d;
    const float* Kp = kh + (size_t)(j0 + l_s) * GD + g * DK + l_d;

    #pragma unroll
    for (int q = 0; q < 8; q++) {
        float4 vq = *(const float4*)(Qp + 4*q);
        vq.x *= 0.125f; vq.y *= 0.125f; vq.z *= 0.125f; vq.w *= 0.125f;
        store_split4(vq, &Qh_s[l_s*72 + l_d + 4*q], &Ql_s[l_s*72 + l_d + 4*q]);
        float4 vk = *(const float4*)(Kp + 4*q);
        store_split4(vk, &Kh_s[l_s*72 + l_d + 4*q], &Kl_s[l_s*72 + l_d + 4*q]);
    }
    __syncthreads();

    FragC acc[2][4];
    #pragma unroll
    for (int i = 0; i < 2; i++)
        #pragma unroll
        for (int j = 0; j < 4; j++)
            wmma::fill_fragment(acc[i][j], 0.0f);

    #pragma unroll
    for (int kf = 0; kf < 4; kf++) {
        FragA a_hi[2], a_lo[2];
        #pragma unroll
        for (int i = 0; i < 2; i++) {
            wmma::load_matrix_sync(a_hi[i], &Qh_s[(m_base + i*16)*72 + kf*16], 72);
            wmma::load_matrix_sync(a_lo[i], &Ql_s[(m_base + i*16)*72 + kf*16], 72);
        }
        #pragma unroll
        for (int j = 0; j < 4; j++) {
            FragBc b_hi, b_lo;
            wmma::load_matrix_sync(b_hi, &Kh_s[(n_base + j*16)*72 + kf*16], 72);
            wmma::load_matrix_sync(b_lo, &Kl_s[(n_base + j*16)*72 + kf*16], 72);
            #pragma unroll
            for (int i = 0; i < 2; i++) {
                wmma::mma_sync(acc[i][j], a_hi[i], b_hi, acc[i][j]);
                wmma::mma_sync(acc[i][j], a_hi[i], b_lo, acc[i][j]);
                wmma::mma_sync(acc[i][j], a_lo[i], b_hi, acc[i][j]);
            }
        }
    }

    // Direct global store of raw scores
    float* ap = attn + (size_t)h * S * S + (size_t)i0 * S + j0;
    #pragma unroll
    for (int i = 0; i < 2; i++)
        #pragma unroll
        for (int j = 0; j < 4; j++)
            wmma::store_matrix_sync(ap + (size_t)(m_base + i*16) * S + n_base + j*16,
                                    acc[i][j], S, wmma::mem_row_major);
}

// ---------------------------------------------------------------------------
// Masked row softmax in place. One block (256 threads) per row of S=2048.
// ---------------------------------------------------------------------------
__device__ __forceinline__ float warp_max(float v) {
    #pragma unroll
    for (int o = 16; o > 0; o >>= 1) v = fmaxf(v, __shfl_xor_sync(0xffffffffu, v, o));
    return v;
}
__device__ __forceinline__ float warp_sum(float v) {
    #pragma unroll
    for (int o = 16; o > 0; o >>= 1) v += __shfl_xor_sync(0xffffffffu, v, o);
    return v;
}

__global__ __launch_bounds__(256)
void softmax_k(float* __restrict__ attn, const unsigned int* __restrict__ mask)
{
    const size_t row = blockIdx.x;          // h*S + i
    const size_t mrow = row & (S - 1);      // i (mask is [1,1,S,S])
    float4* p = (float4*)(attn + row * (size_t)S);
    const uint4* mp = (const uint4*)(mask + mrow * (size_t)S);
    const int t = threadIdx.x;
    const int warp = t >> 5, lane = t & 31;
    __shared__ float red[8];

    float4 v0 = p[t];
    float4 v1 = p[t + 256];
    uint4 m0v = mp[t];
    uint4 m1v = mp[t + 256];
    v0.x = m0v.x ? v0.x : -1e9f;
    v0.y = m0v.y ? v0.y : -1e9f;
    v0.z = m0v.z ? v0.z : -1e9f;
    v0.w = m0v.w ? v0.w : -1e9f;
    v1.x = m1v.x ? v1.x : -1e9f;
    v1.y = m1v.y ? v1.y : -1e9f;
    v1.z = m1v.z ? v1.z : -1e9f;
    v1.w = m1v.w ? v1.w : -1e9f;

    float m = fmaxf(fmaxf(fmaxf(v0.x, v0.y), fmaxf(v0.z, v0.w)),
                    fmaxf(fmaxf(v1.x, v1.y), fmaxf(v1.z, v1.w)));
    m = warp_max(m);
    if (lane == 0) red[warp] = m;
    __syncthreads();
    m = red[lane & 7];
    m = warp_max(m);

    v0.x = expf(v0.x - m); v0.y = expf(v0.y - m);
    v0.z = expf(v0.z - m); v0.w = expf(v0.w - m);
    v1.x = expf(v1.x - m); v1.y = expf(v1.y - m);
    v1.z = expf(v1.z - m); v1.w = expf(v1.w - m);

    float s = v0.x + v0.y + v0.z + v0.w + v1.x + v1.y + v1.z + v1.w;
    s = warp_sum(s);
    __syncthreads();
    if (lane == 0) red[warp] = s;
    __syncthreads();
    s = (lane < 8) ? red[lane] : 0.0f;
    s = warp_sum(s);
    const float inv = 1.0f / s;

    v0.x *= inv; v0.y *= inv; v0.z *= inv; v0.w *= inv;
    v1.x *= inv; v1.y *= inv; v1.z *= inv; v1.w *= inv;
    p[t] = v0;
    p[t + 256] = v1;
}

// ---------------------------------------------------------------------------
// PV: outh[i, h*64+d] = sum_j attn[h,i,j] * Vg[j,d]
// 128x64 tile, BK=32, warp tile 32x32 (4x2 warps).
// ---------------------------------------------------------------------------
__global__ __launch_bounds__(256)
void pv_k(const float* __restrict__ attn,
          const float* __restrict__ vh,
          float* __restrict__ outh)
{
    __shared__ __align__(16) __nv_bfloat16 As_hi[128][40];
    __shared__ __align__(16) __nv_bfloat16 As_lo[128][40];
    __shared__ __align__(16) __nv_bfloat16 Bs_hi[32][72];
    __shared__ __align__(16) __nv_bfloat16 Bs_lo[32][72];

    const int tid  = threadIdx.x;
    const int warp = tid >> 5;
    const int i0 = blockIdx.x * 128;
    const int h  = blockIdx.y;
    const int g  = h >> 2;
    const int wm = warp >> 1;
    const int wn = warp & 1;
    const int m_base = wm * 32;
    const int n_base = wn * 32;

    const int la_m  = tid >> 1;
    const int la_k4 = (tid & 1) * 16;
    const int lb_k  = tid >> 3;
    const int lb_n  = (tid & 7) * 8;

    const float* Ap = attn + (size_t)h * S * S + (size_t)(i0 + la_m) * S + la_k4;
    const float* Bp = vh + (size_t)lb_k * GD + g * DK + lb_n;

    FragC acc[2][2];
    #pragma unroll
    for (int i = 0; i < 2; i++)
        #pragma unroll
        for (int j = 0; j < 2; j++)
            wmma::fill_fragment(acc[i][j], 0.0f);

    float4 pa[4], pb[2];
    #pragma unroll
    for (int q = 0; q < 4; q++) pa[q] = *(const float4*)(Ap + 4*q);
    #pragma unroll
    for (int q = 0; q < 2; q++) pb[q] = *(const float4*)(Bp + 4*q);

    for (int k0 = 0; k0 < S; k0 += 32) {
        #pragma unroll
        for (int q = 0; q < 4; q++)
            store_split4(pa[q], &As_hi[la_m][la_k4 + 4*q], &As_lo[la_m][la_k4 + 4*q]);
        #pragma unroll
        for (int q = 0; q < 2; q++)
            store_split4(pb[q], &Bs_hi[lb_k][lb_n + 4*q], &Bs_lo[lb_k][lb_n + 4*q]);
        __syncthreads();

        if (k0 + 32 < S) {
            #pragma unroll
            for (int q = 0; q < 4; q++) pa[q] = *(const float4*)(Ap + k0 + 32 + 4*q);
            #pragma unroll
            for (int q = 0; q < 2; q++) pb[q] = *(const float4*)(Bp + (size_t)(k0 + 32) * GD + 4*q);
        }

        #pragma unroll
        for (int kf = 0; kf < 2; kf++) {
            FragA a_hi[2], a_lo[2];
            #pragma unroll
            for (int i = 0; i < 2; i++) {
                wmma::load_matrix_sync(a_hi[i], &As_hi[m_base + i*16][kf*16], 40);
                wmma::load_matrix_sync(a_lo[i], &As_lo[m_base + i*16][kf*16], 40);
            }
            #pragma unroll
            for (int j = 0; j < 2; j++) {
                FragBr b_hi, b_lo;
                wmma::load_matrix_sync(b_hi, &Bs_hi[kf*16][n_base + j*16], 72);
                wmma::load_matrix_sync(b_lo, &Bs_lo[kf*16][n_base + j*16], 72);
                #pragma unroll
                for (int i = 0; i < 2; i++) {
                    wmma::mma_sync(acc[i][j], a_hi[i], b_hi, acc[i][j]);
                    wmma::mma_sync(acc[i][j], a_hi[i], b_lo, acc[i][j]);
                    wmma::mma_sync(acc[i][j], a_lo[i], b_hi, acc[i][j]);
                }
            }
        }
        __syncthreads();
    }

    #pragma unroll
    for (int i = 0; i < 2; i++)
        #pragma unroll
        for (int j = 0; j < 2; j++)
            wmma::store_matrix_sync(outh + (size_t)(i0 + m_base + i*16) * HD + h * DK + n_base + j*16,
                                    acc[i][j], HD, wmma::mem_row_major);
}

// ---------------------------------------------------------------------------
extern "C" void kernel_launch(void* const* d_in, const int* in_sizes, int n_in,
                              void* d_out, int out_size)
{
    const float*        q    = (const float*)d_in[0];
    const float*        k    = (const float*)d_in[1];
    const float*        v    = (const float*)d_in[2];
    const unsigned int* mask = (const unsigned int*)d_in[3];
    const float*        wq   = (const float*)d_in[4];
    const float*        bq   = (const float*)d_in[5];
    const float*        wk   = (const float*)d_in[6];
    const float*        bk   = (const float*)d_in[7];
    const float*        wv   = (const float*)d_in[8];
    const float*        bv   = (const float*)d_in[9];
    const float*        wo   = (const float*)d_in[10];
    const float*        bo   = (const float*)d_in[11];

    float* out  = (float*)d_out;
    float* attn = out + (size_t)S * DM;   // outputs: [out | attn]

    float *qh, *kh, *vh, *outh;
    cudaGetSymbolAddress((void**)&qh,   g_qh);
    cudaGetSymbolAddress((void**)&kh,   g_kh);
    cudaGetSymbolAddress((void**)&vh,   g_vh);
    cudaGetSymbolAddress((void**)&outh, g_outh);

    const int scores_smem = 4 * 128 * 72 * (int)sizeof(__nv_bfloat16);  // 73728
    cudaFuncSetAttribute(scores_k, cudaFuncAttributeMaxDynamicSharedMemorySize, scores_smem);

    // Projections
    gemm_bias_k<<<dim3(HD / 128, S / 128), 256>>>(q, wq, bq, qh, S, HD, DM);
    gemm_bias_k<<<dim3(GD / 128, S / 128), 256>>>(k, wk, bk, kh, S, GD, DM);
    gemm_bias_k<<<dim3(GD / 128, S / 128), 256>>>(v, wv, bv, vh, S, GD, DM);

    // Raw scaled scores (no mask) straight to attn region
    scores_k<<<dim3(S / 128, S / 128, H), 256, scores_smem>>>(qh, kh, attn);

    // Masked row softmax in place
    softmax_k<<<H * S, 256>>>(attn, mask);

    // attn @ V
    pv_k<<<dim3(S / 128, H), 256>>>(attn, vh, outh);

    // Output projection
    gemm_bias_k<<<dim3(DM / 128, S / 128), 256>>>(outh, wo, bo, out, S, DM, HD);
}